// round 3
// baseline (speedup 1.0000x reference)
#include <cuda_runtime.h>
#include <cuda_bf16.h>
#include <cstdint>

// Problem dims
#define TT 2048
#define BB 16
#define II 512
#define HH 512
#define BH (BB*HH)   // 8192

// ---------------------------------------------------------------------------
// Inter-CTA barrier state: 4 independent batch-groups, monotone counters.
// Reset by the xproj kernel (runs first in the stream each launch).
// ---------------------------------------------------------------------------
__device__ unsigned int g_bar[4];

static __device__ __forceinline__ unsigned int ld_acquire_gpu(const unsigned int* p) {
    unsigned int v;
    asm volatile("ld.acquire.gpu.u32 %0, [%1];" : "=r"(v) : "l"(p) : "memory");
    return v;
}

// ---------------------------------------------------------------------------
// Kernel 1: x_proj[t,b,h] = sum_i inputs[t,b,i] * weight[h][512+i] + bias[h]
// GEMM: M = T*B = 32768 (row-major, K contiguous), N = 512, K = 512.
// Tile 128x64, K-step 32, 256 threads, 8x4 microtile. Writes into out[0..T*B*H).
// ---------------------------------------------------------------------------
__global__ __launch_bounds__(256)
void xproj_kernel(const float* __restrict__ A,      // inputs [M][512]
                  const float* __restrict__ W,      // weight [512][1024]
                  const float* __restrict__ bias,   // [512]
                  float* __restrict__ out)          // [M][512]
{
    // reset scan barriers (stream-ordered before the scan kernel)
    if (blockIdx.x == 0 && blockIdx.y == 0 && threadIdx.x < 4)
        g_bar[threadIdx.x] = 0u;

    __shared__ float As[32][132];  // [k][m], padded
    __shared__ float Bs[32][68];   // [k][n], padded

    const int tid = threadIdx.x;
    const int bm = blockIdx.x * 128;
    const int bn = blockIdx.y * 64;

    const int tx = tid & 15;   // n group
    const int ty = tid >> 4;   // m group

    float acc[8][4];
#pragma unroll
    for (int r = 0; r < 8; r++)
#pragma unroll
        for (int c = 0; c < 4; c++) acc[r][c] = 0.f;

#pragma unroll 1
    for (int kt = 0; kt < 16; kt++) {
        const int k0 = kt * 32;
        // load A tile: 128 rows x 32 k  = 1024 float4, 4 per thread
#pragma unroll
        for (int j = 0; j < 4; j++) {
            int idx = tid + j * 256;          // [0,1024)
            int row = idx >> 3;
            int q   = idx & 7;
            float4 v = *reinterpret_cast<const float4*>(&A[(size_t)(bm + row) * 512 + k0 + q * 4]);
            As[q * 4 + 0][row] = v.x;
            As[q * 4 + 1][row] = v.y;
            As[q * 4 + 2][row] = v.z;
            As[q * 4 + 3][row] = v.w;
        }
        // load B tile (w_xh): 64 rows x 32 k = 512 float4, 2 per thread
#pragma unroll
        for (int j = 0; j < 2; j++) {
            int idx = tid + j * 256;          // [0,512)
            int row = idx >> 3;
            int q   = idx & 7;
            float4 v = *reinterpret_cast<const float4*>(&W[(size_t)(bn + row) * 1024 + 512 + k0 + q * 4]);
            Bs[q * 4 + 0][row] = v.x;
            Bs[q * 4 + 1][row] = v.y;
            Bs[q * 4 + 2][row] = v.z;
            Bs[q * 4 + 3][row] = v.w;
        }
        __syncthreads();

#pragma unroll
        for (int k = 0; k < 32; k++) {
            float4 a0 = *reinterpret_cast<const float4*>(&As[k][ty * 8]);
            float4 a1 = *reinterpret_cast<const float4*>(&As[k][ty * 8 + 4]);
            float4 b  = *reinterpret_cast<const float4*>(&Bs[k][tx * 4]);
            float av[8] = {a0.x, a0.y, a0.z, a0.w, a1.x, a1.y, a1.z, a1.w};
            float bv[4] = {b.x, b.y, b.z, b.w};
#pragma unroll
            for (int r = 0; r < 8; r++)
#pragma unroll
                for (int c = 0; c < 4; c++)
                    acc[r][c] = fmaf(av[r], bv[c], acc[r][c]);
        }
        __syncthreads();
    }

    // epilogue with bias
#pragma unroll
    for (int r = 0; r < 8; r++) {
        size_t row = (size_t)(bm + ty * 8 + r) * 512 + bn + tx * 4;
#pragma unroll
        for (int c = 0; c < 4; c++)
            out[row + c] = acc[r][c] + bias[bn + tx * 4 + c];
    }
}

// ---------------------------------------------------------------------------
// Kernel 2: persistent scan.
// 128 CTAs = 4 batch-groups (4 batches each) x 32 col-groups (16 cols each).
// W_hh slice resident in SMEM (32 KB). h_t flows through out[] (L2 via .cg).
// Per batch-group barrier: monotone atomic counter in g_bar[bg].
// ---------------------------------------------------------------------------
__global__ __launch_bounds__(256)
void scan_kernel(const float* __restrict__ weight,  // [512][1024], w_hh = cols [0,512)
                 const float* __restrict__ state,   // [16][512]
                 float* __restrict__ out)           // [T][16][512] + last [16][512]
{
    __shared__ float Wsh[512][16];   // [k][col]  32 KB
    __shared__ float hsh[4][512];    // [b_local][k]  8 KB
    __shared__ float red[16][64];    // [ks][col*4+b]  4 KB

    const int tid = threadIdx.x;
    const int cg  = blockIdx.x & 31;   // column group: cols [cg*16, cg*16+16)
    const int bg  = blockIdx.x >> 5;   // batch group:  batches [bg*4, bg*4+4)
    const int b0  = bg * 4;

    const int col = tid & 15;
    const int ks  = tid >> 4;          // 16 k-splits of 32

    // Load W_hh slice once: Wsh[k][c] = weight[(cg*16+c)][k]
    {
        const int c = tid & 15;
        const int kk = tid >> 4;
#pragma unroll
        for (int j = 0; j < 8; j++) {
            int k = kk * 32 + j * 4;
            float4 w = *reinterpret_cast<const float4*>(&weight[(size_t)(cg * 16 + c) * 1024 + k]);
            Wsh[k + 0][c] = w.x;
            Wsh[k + 1][c] = w.y;
            Wsh[k + 2][c] = w.z;
            Wsh[k + 3][c] = w.w;
        }
    }
    __syncthreads();

    unsigned int* bar = &g_bar[bg];
    const int kbase = ks * 32;

#pragma unroll 1
    for (int t = 0; t < TT; t++) {
        // ---- stage h_{t-1} for this batch group into SMEM (L2-only loads) ----
        const float* hsrc = (t == 0) ? (state + (size_t)b0 * HH)
                                     : (out + (size_t)(t - 1) * BH + (size_t)b0 * HH);
        {
            // 2048 floats = 512 float4, 2 per thread, no transpose
            int i0 = tid, i1 = tid + 256;
            float4 v0 = __ldcg(reinterpret_cast<const float4*>(hsrc) + i0);
            float4 v1 = __ldcg(reinterpret_cast<const float4*>(hsrc) + i1);
            *reinterpret_cast<float4*>(&hsh[0][0] + i0 * 4) = v0;
            *reinterpret_cast<float4*>(&hsh[0][0] + i1 * 4) = v1;
        }
        __syncthreads();

        // ---- compute partial dot products: acc[b] over k in [kbase, kbase+32) ----
        float acc0 = 0.f, acc1 = 0.f, acc2 = 0.f, acc3 = 0.f;
#pragma unroll
        for (int kc = 0; kc < 8; kc++) {
            const int k = kbase + kc * 4;
            float4 h0 = *reinterpret_cast<const float4*>(&hsh[0][k]);
            float4 h1 = *reinterpret_cast<const float4*>(&hsh[1][k]);
            float4 h2 = *reinterpret_cast<const float4*>(&hsh[2][k]);
            float4 h3 = *reinterpret_cast<const float4*>(&hsh[3][k]);
            float w0 = Wsh[k + 0][col];
            float w1 = Wsh[k + 1][col];
            float w2 = Wsh[k + 2][col];
            float w3 = Wsh[k + 3][col];
            acc0 = fmaf(w0, h0.x, acc0); acc0 = fmaf(w1, h0.y, acc0);
            acc0 = fmaf(w2, h0.z, acc0); acc0 = fmaf(w3, h0.w, acc0);
            acc1 = fmaf(w0, h1.x, acc1); acc1 = fmaf(w1, h1.y, acc1);
            acc1 = fmaf(w2, h1.z, acc1); acc1 = fmaf(w3, h1.w, acc1);
            acc2 = fmaf(w0, h2.x, acc2); acc2 = fmaf(w1, h2.y, acc2);
            acc2 = fmaf(w2, h2.z, acc2); acc2 = fmaf(w3, h2.w, acc2);
            acc3 = fmaf(w0, h3.x, acc3); acc3 = fmaf(w1, h3.y, acc3);
            acc3 = fmaf(w2, h3.z, acc3); acc3 = fmaf(w3, h3.w, acc3);
        }

        // ---- reduce 16 k-splits ----
        *reinterpret_cast<float4*>(&red[ks][col * 4]) = make_float4(acc0, acc1, acc2, acc3);
        __syncthreads();

        if (tid < 64) {
            const int c = tid & 15;
            const int b = tid >> 4;
            float s = 0.f;
#pragma unroll
            for (int r = 0; r < 16; r++) s += red[r][c * 4 + b];
            const size_t off = (size_t)t * BH + (size_t)(b0 + b) * HH + cg * 16 + c;
            const float xp = __ldcg(out + off);   // x_proj written by kernel 1
            const float hn = s + xp;
            __stcg(out + off, hn);                // out[t] := h_t (L2, bypass L1)
            if (t == TT - 1)
                __stcg(out + (size_t)TT * BH + (size_t)(b0 + b) * HH + cg * 16 + c, hn);
            __threadfence();                      // make h_t visible gpu-wide
        }
        __syncthreads();

        // ---- batch-group barrier (32 CTAs), monotone counter ----
        if (tid == 0) {
            atomicAdd(bar, 1u);
            const unsigned int target = 32u * (unsigned int)(t + 1);
            while (ld_acquire_gpu(bar) < target) { /* spin on L2 */ }
        }
        __syncthreads();
    }
}

// ---------------------------------------------------------------------------
// Launch
// ---------------------------------------------------------------------------
extern "C" void kernel_launch(void* const* d_in, const int* in_sizes, int n_in,
                              void* d_out, int out_size) {
    const float* inputs = (const float*)d_in[0];  // [T][B][I]
    const float* state  = (const float*)d_in[1];  // [B][H]
    const float* weight = (const float*)d_in[2];  // [H][I+H]
    const float* bias   = (const float*)d_in[3];  // [H]
    float* out = (float*)d_out;                   // [T][B][H] outputs, then [B][H] last

    // Phase 1: x_proj into out[0 .. T*B*H)
    dim3 g1(256, 8);  // M/128 x N/64
    xproj_kernel<<<g1, 256>>>(inputs, weight, bias, out);

    // Phase 2: sequential scan over T, persistent 128-CTA kernel
    scan_kernel<<<128, 256>>>(weight, state, out);

    (void)in_sizes; (void)n_in; (void)out_size;
}